// round 8
// baseline (speedup 1.0000x reference)
#include <cuda_runtime.h>
#include <cstdint>

#define NSTEPS 2176
#define BURN   128
#define DWALK  512
#define HMLP   1024

// ---------------- scratch (no allocations allowed) ----------------
__device__ __align__(16) float g_M [NSTEPS * DWALK];   // 0.1 * noise_t  [2176,512]
__device__ __align__(16) float g_ZD[NSTEPS * HMLP];    // M @ W1         [2176,1024]
__device__ float g_U[NSTEPS];                          // uniform u_t

// ---------------- threefry2x32 (Random123 / JAX exact) ----------------
__device__ __forceinline__ uint32_t rotl32(uint32_t x, int r) {
    return (x << r) | (x >> (32 - r));
}

__device__ __forceinline__ void threefry2x32(uint32_t k0, uint32_t k1,
                                             uint32_t c0, uint32_t c1,
                                             uint32_t& o0, uint32_t& o1) {
    uint32_t ks2 = 0x1BD11BDAu ^ k0 ^ k1;
    uint32_t x0 = c0 + k0;
    uint32_t x1 = c1 + k1;
#define TF_RND(r) { x0 += x1; x1 = rotl32(x1, r); x1 ^= x0; }
    TF_RND(13) TF_RND(15) TF_RND(26) TF_RND(6)
    x0 += k1;  x1 += ks2 + 1u;
    TF_RND(17) TF_RND(29) TF_RND(16) TF_RND(24)
    x0 += ks2; x1 += k0 + 2u;
    TF_RND(13) TF_RND(15) TF_RND(26) TF_RND(6)
    x0 += k0;  x1 += k1 + 3u;
    TF_RND(17) TF_RND(29) TF_RND(16) TF_RND(24)
    x0 += k1;  x1 += ks2 + 4u;
    TF_RND(13) TF_RND(15) TF_RND(26) TF_RND(6)
    x0 += ks2; x1 += k0 + 5u;
#undef TF_RND
    o0 = x0; o1 = x1;
}

// bits -> float in [0,1): ((b>>9)|0x3f800000) as float - 1  (JAX _uniform)
__device__ __forceinline__ float bits_to_f01(uint32_t b) {
    return __fadd_rn(__uint_as_float((b >> 9) | 0x3F800000u), -1.0f);
}

// XLA ErfInv f32 (Giles polynomial; XLA emits mul+add WITHOUT fma contraction)
__device__ __forceinline__ float erfinv_xla(float x) {
    float w = -log1pf(-__fmul_rn(x, x));
    float p;
    if (w < 5.0f) {
        w = __fadd_rn(w, -2.5f);
        p = 2.81022636e-08f;
        p = __fadd_rn(__fmul_rn(p, w), 3.43273939e-07f);
        p = __fadd_rn(__fmul_rn(p, w), -3.5233877e-06f);
        p = __fadd_rn(__fmul_rn(p, w), -4.39150654e-06f);
        p = __fadd_rn(__fmul_rn(p, w), 0.00021858087f);
        p = __fadd_rn(__fmul_rn(p, w), -0.00125372503f);
        p = __fadd_rn(__fmul_rn(p, w), -0.00417768164f);
        p = __fadd_rn(__fmul_rn(p, w), 0.246640727f);
        p = __fadd_rn(__fmul_rn(p, w), 1.50140941f);
    } else {
        w = __fadd_rn(__fsqrt_rn(w), -3.0f);
        p = -0.000200214257f;
        p = __fadd_rn(__fmul_rn(p, w), 0.000100950558f);
        p = __fadd_rn(__fmul_rn(p, w), 0.00134934322f);
        p = __fadd_rn(__fmul_rn(p, w), -0.00367342844f);
        p = __fadd_rn(__fmul_rn(p, w), 0.00573950773f);
        p = __fadd_rn(__fmul_rn(p, w), -0.0076224613f);
        p = __fadd_rn(__fmul_rn(p, w), 0.00943887047f);
        p = __fadd_rn(__fmul_rn(p, w), 1.00167406f);
        p = __fadd_rn(__fmul_rn(p, w), 2.83297682f);
    }
    return __fmul_rn(p, x);
}

// JAX normal: u = uniform(key, lo=nextafter(-1,0), hi=1); sqrt(2)*erfinv(u)
__device__ __forceinline__ float normal_from_bits(uint32_t b) {
    const float lo = -0.99999994f;  // nextafter(-1f, 0f)
    float f = bits_to_f01(b);
    float u = fmaxf(lo, __fadd_rn(__fmul_rn(f, 2.0f), lo));
    return __fmul_rn(1.4142135381698608f, erfinv_xla(u));  // float32(sqrt(2))
}

// XLA Tanh f32 emitter (clamp 7.90531110763549805, rational poly, no fma)
__device__ __forceinline__ float tanh_xla(float x) {
    const float kClamp = 7.90531110763549805f;
    float xc = fminf(fmaxf(x, -kClamp), kClamp);
    float x2 = __fmul_rn(xc, xc);
    float p = -2.76076847742355e-16f;
    p = __fadd_rn(__fmul_rn(p, x2), 2.00018790482477e-13f);
    p = __fadd_rn(__fmul_rn(p, x2), -8.60467152213735e-11f);
    p = __fadd_rn(__fmul_rn(p, x2), 5.12229709037114e-08f);
    p = __fadd_rn(__fmul_rn(p, x2), 1.48572235717979e-05f);
    p = __fadd_rn(__fmul_rn(p, x2), 6.37261928875436e-04f);
    p = __fadd_rn(__fmul_rn(p, x2), 4.89352455891786e-03f);
    float num = __fmul_rn(xc, p);
    float q = 1.19825839466702e-06f;
    q = __fadd_rn(__fmul_rn(q, x2), 1.18534705686654e-04f);
    q = __fadd_rn(__fmul_rn(q, x2), 2.26843463243900e-03f);
    q = __fadd_rn(__fmul_rn(q, x2), 4.89352518554385e-03f);
    float r = __fdiv_rn(num, q);
    return (fabsf(x) < 0.0004f) ? x : r;
}

// ---------------- kernel 1: per-step keys, uniforms, normals ----------------
// jax_threefry_partitionable=True semantics (verified passing R3/R6):
//   split(key, n)[t]             = output pair of TF(key, (0, t))
//   random_bits(key,32,shape)[i] = o0 ^ o1 of TF(key, (0, i))
__global__ void gen_kernel() {
    int t = blockIdx.x;
    int i = threadIdx.x;  // 0..511

    uint32_t kt0, kt1, kn0, kn1;
    threefry2x32(0u, 1u, 0u, (uint32_t)t, kt0, kt1);
    threefry2x32(kt0, kt1, 0u, 0u, kn0, kn1);

    if (i == 0) {
        uint32_t ku0, ku1, ua, ub;
        threefry2x32(kt0, kt1, 0u, 1u, ku0, ku1);
        threefry2x32(ku0, ku1, 0u, 0u, ua, ub);
        g_U[t] = bits_to_f01(ua ^ ub);
    }

    uint32_t r0, r1;
    threefry2x32(kn0, kn1, 0u, (uint32_t)i, r0, r1);
    g_M[t * DWALK + i] = __fmul_rn(normal_from_bits(r0 ^ r1), 0.1f);
}

// ---------------- kernel 2: fp32 SGEMM  ZD = M @ W1 ----------------
// 128x128x8 tile, 256 threads, 8x8 per-thread microtile. 136 blocks ~ 1 wave.
__global__ void __launch_bounds__(256) gemm_kernel(const float* __restrict__ W1) {
    __shared__ float As[8][128];
    __shared__ float Bs[8][128];

    int tid = threadIdx.x;
    int tx = tid & 15;
    int ty = tid >> 4;
    int rowBase = blockIdx.y * 128;
    int colBase = blockIdx.x * 128;

    int aRow = tid >> 1;
    int aK   = (tid & 1) * 4;
    int bK   = tid >> 5;
    int bCol = (tid & 31) * 4;

    float acc[8][8] = {{0.f}};

    for (int k0 = 0; k0 < 512; k0 += 8) {
        float4 av = *reinterpret_cast<const float4*>(&g_M[(rowBase + aRow) * 512 + k0 + aK]);
        float4 bv = *reinterpret_cast<const float4*>(&W1[(k0 + bK) * 1024 + colBase + bCol]);
        As[aK + 0][aRow] = av.x;
        As[aK + 1][aRow] = av.y;
        As[aK + 2][aRow] = av.z;
        As[aK + 3][aRow] = av.w;
        *reinterpret_cast<float4*>(&Bs[bK][bCol]) = bv;
        __syncthreads();
#pragma unroll
        for (int k = 0; k < 8; k++) {
            float4 a0 = *reinterpret_cast<float4*>(&As[k][ty * 8]);
            float4 a1 = *reinterpret_cast<float4*>(&As[k][ty * 8 + 4]);
            float4 b0 = *reinterpret_cast<float4*>(&Bs[k][tx * 8]);
            float4 b1 = *reinterpret_cast<float4*>(&Bs[k][tx * 8 + 4]);
            float ar[8] = {a0.x, a0.y, a0.z, a0.w, a1.x, a1.y, a1.z, a1.w};
            float br[8] = {b0.x, b0.y, b0.z, b0.w, b1.x, b1.y, b1.z, b1.w};
#pragma unroll
            for (int i = 0; i < 8; i++)
#pragma unroll
                for (int j = 0; j < 8; j++)
                    acc[i][j] = fmaf(ar[i], br[j], acc[i][j]);
        }
        __syncthreads();
    }
#pragma unroll
    for (int i = 0; i < 8; i++) {
        int r = rowBase + ty * 8 + i;
        *reinterpret_cast<float4*>(&g_ZD[r * 1024 + colBase + tx * 8]) =
            make_float4(acc[i][0], acc[i][1], acc[i][2], acc[i][3]);
        *reinterpret_cast<float4*>(&g_ZD[r * 1024 + colBase + tx * 8 + 4]) =
            make_float4(acc[i][4], acc[i][5], acc[i][6], acc[i][7]);
    }
}

// ---------------- kernel 3: speculative pipelined MH chain (1 CTA, 512 threads) ----
// Iteration t: decides step t from partials computed in iteration t-1 (both
// accept/reject candidates), and computes tanh+warp-reduce partials for BOTH
// step-(t+1) candidates. Inter-iteration critical path = select + div + cmp.
// All arithmetic bit-identical to the R5 kernel (same association, same order).
__global__ void __launch_bounds__(512, 1)
chain_kernel(const float* __restrict__ x0, const float* __restrict__ W1,
             const float* __restrict__ b1, const float* __restrict__ W2,
             const float* __restrict__ b2, float* __restrict__ out) {
    __shared__ float s_x0[DWALK];
    __shared__ __align__(16) float s_part[2][2][16];   // [parity][cand A/B][warp]

    int tid  = threadIdx.x;          // 0..511
    int lane = tid & 31;
    int wid  = tid >> 5;             // 0..15

    s_x0[tid] = x0[tid];
    __syncthreads();

    // z0 components = dot(x0, W1[:, 2*tid]), dot(x0, W1[:, 2*tid+1])
    float zc0 = 0.f, zc1 = 0.f;
#pragma unroll 8
    for (int k = 0; k < DWALK; k++) {
        float xv = s_x0[k];
        float2 w = *reinterpret_cast<const float2*>(&W1[k * 1024 + 2 * tid]);
        zc0 = fmaf(xv, w.x, zc0);
        zc1 = fmaf(xv, w.y, zc1);
    }

    float2 b1v = *reinterpret_cast<const float2*>(&b1[2 * tid]);
    float2 w2v = *reinterpret_cast<const float2*>(&W2[2 * tid]);
    float  b2v = b2[0];
    float  x   = s_x0[tid];

    auto tree16 = [&](const float* sp) -> float {
        float4 q0 = *reinterpret_cast<const float4*>(sp);
        float4 q1 = *reinterpret_cast<const float4*>(sp + 4);
        float4 q2 = *reinterpret_cast<const float4*>(sp + 8);
        float4 q3 = *reinterpret_cast<const float4*>(sp + 12);
        float s0 = __fadd_rn(__fadd_rn(q0.x, q0.y), __fadd_rn(q0.z, q0.w));
        float s1 = __fadd_rn(__fadd_rn(q1.x, q1.y), __fadd_rn(q1.z, q1.w));
        float s2 = __fadd_rn(__fadd_rn(q2.x, q2.y), __fadd_rn(q2.z, q2.w));
        float s3 = __fadd_rn(__fadd_rn(q3.x, q3.y), __fadd_rn(q3.z, q3.w));
        return __fadd_rn(__fadd_rn(s0, s1), __fadd_rn(s2, s3));
    };

    // ---- p_old = psi2(x0): partials into s_part[1][1] (overwritten in iter 0) ----
    float p_old;
    {
        float h0 = tanh_xla(__fadd_rn(zc0, b1v.x));
        float h1 = tanh_xla(__fadd_rn(zc1, b1v.y));
        float pv = __fadd_rn(__fmul_rn(h0, w2v.x), __fmul_rn(h1, w2v.y));
#pragma unroll
        for (int o = 16; o > 0; o >>= 1) pv += __shfl_down_sync(0xffffffffu, pv, o);
        if (lane == 0) s_part[1][1][wid] = pv;
        __syncthreads();
        float mdl = __fadd_rn(tree16(s_part[1][1]), b2v);
        p_old = __fmul_rn(mdl, mdl);
    }
    __syncthreads();   // all threads done reading s_part[1][1] before iter 0 rewrites it

    // ---- prologue: step-0 proposal (both candidates identical, prev_acc=false) ----
    float2 zdrow = *reinterpret_cast<const float2*>(&g_ZD[2 * tid]);   // ZD row 0
    float cB0 = __fadd_rn(zc0, zdrow.x);       // z0 + zd_0  (reject-branch candidate)
    float cB1 = __fadd_rn(zc1, zdrow.y);
    float cA0 = cB0, cA1 = cB1;
    {
        float h0 = tanh_xla(__fadd_rn(cB0, b1v.x));
        float h1 = tanh_xla(__fadd_rn(cB1, b1v.y));
        float pv = __fadd_rn(__fmul_rn(h0, w2v.x), __fmul_rn(h1, w2v.y));
#pragma unroll
        for (int o = 16; o > 0; o >>= 1) pv += __shfl_down_sync(0xffffffffu, pv, o);
        if (lane == 0) { s_part[0][0][wid] = pv; s_part[0][1][wid] = pv; }
        // loop-top __syncthreads() makes these visible
    }

    // carried state
    float zold0 = zc0, zold1 = zc1;        // z_{t-1} (resolved chain pre-activation)
    float zsel0 = zc0, zsel1 = zc1;        // znew_{t-1} (prev proposal; unused when prev_acc=0)
    bool  prev_acc = false;

    // prefetches: uval/mval for step 0; zd_cand = ZD row 1 (builds step-1 candidates)
    float uval = g_U[0];
    float mval = g_M[tid];
    float2 zd_cand = *reinterpret_cast<const float2*>(&g_ZD[1 * HMLP + 2 * tid]);

    for (int t = 0; t < NSTEPS; t++) {
        __syncthreads();   // partials for step t (written iter t-1 / prologue) visible

        // --- decision for step t (reads last iteration's partials) ---
        float sA = tree16(s_part[t & 1][0]);
        float sB = tree16(s_part[t & 1][1]);

        // --- prefetch future rows (independent of decisions) ---
        float2 zd_n = make_float2(0.f, 0.f);
        float  m_n = 0.f, u_n = 0.f;
        if (t + 2 < NSTEPS)
            zd_n = *reinterpret_cast<const float2*>(&g_ZD[(t + 2) * HMLP + 2 * tid]);
        if (t + 1 < NSTEPS) {
            m_n = g_M[(t + 1) * DWALK + tid];
            u_n = g_U[t + 1];
        }

        float mdlA = __fadd_rn(sA, b2v);
        float pA   = __fmul_rn(mdlA, mdlA);
        float mdlB = __fadd_rn(sB, b2v);
        float pB   = __fmul_rn(mdlB, mdlB);

        float p_new = prev_acc ? pA : pB;
        float znew0 = prev_acc ? cA0 : cB0;   // resolved proposal pre-activation
        float znew1 = prev_acc ? cA1 : cB1;
        float zt0   = prev_acc ? zsel0 : zold0;  // resolved z_t
        float zt1   = prev_acc ? zsel1 : zold1;

        float ratio = fminf(__fdiv_rn(p_new, __fadd_rn(p_old, 1e-12f)), 1.0f);
        bool  acc   = (uval < ratio);

        if (acc) { p_old = p_new; x = __fadd_rn(x, mval); }
        if (t >= BURN) out[(t - BURN) * DWALK + tid] = x;

        // --- speculative candidates for step t+1 (bulk; independent of acc) ---
        float nA0 = __fadd_rn(znew0, zd_cand.x);   // accept branch: znew_t + zd_{t+1}
        float nA1 = __fadd_rn(znew1, zd_cand.y);
        float nB0 = __fadd_rn(zt0,   zd_cand.x);   // reject branch: z_t + zd_{t+1}
        float nB1 = __fadd_rn(zt1,   zd_cand.y);

        float hA0 = tanh_xla(__fadd_rn(nA0, b1v.x));
        float hA1 = tanh_xla(__fadd_rn(nA1, b1v.y));
        float hB0 = tanh_xla(__fadd_rn(nB0, b1v.x));
        float hB1 = tanh_xla(__fadd_rn(nB1, b1v.y));
        float pvA = __fadd_rn(__fmul_rn(hA0, w2v.x), __fmul_rn(hA1, w2v.y));
        float pvB = __fadd_rn(__fmul_rn(hB0, w2v.x), __fmul_rn(hB1, w2v.y));
#pragma unroll
        for (int o = 16; o > 0; o >>= 1) {
            pvA += __shfl_down_sync(0xffffffffu, pvA, o);
            pvB += __shfl_down_sync(0xffffffffu, pvB, o);
        }
        if (lane == 0) {
            s_part[(t + 1) & 1][0][wid] = pvA;
            s_part[(t + 1) & 1][1][wid] = pvB;
        }

        // --- carry ---
        zold0 = zt0;  zold1 = zt1;
        zsel0 = znew0; zsel1 = znew1;
        cA0 = nA0; cA1 = nA1; cB0 = nB0; cB1 = nB1;
        prev_acc = acc;
        zd_cand = zd_n; mval = m_n; uval = u_n;
    }
}

// ---------------- launch ----------------
extern "C" void kernel_launch(void* const* d_in, const int* in_sizes, int n_in,
                              void* d_out, int out_size) {
    const float* x0 = (const float*)d_in[0];
    const float* W1 = (const float*)d_in[1];
    const float* b1 = (const float*)d_in[2];
    const float* W2 = (const float*)d_in[3];
    const float* b2 = (const float*)d_in[4];
    float* out = (float*)d_out;

    gen_kernel<<<NSTEPS, DWALK>>>();
    gemm_kernel<<<dim3(HMLP / 128, NSTEPS / 128), 256>>>(W1);
    chain_kernel<<<1, 512>>>(x0, W1, b1, W2, b2, out);
}

// round 9
// speedup vs baseline: 1.3757x; 1.3757x over previous
#include <cuda_runtime.h>
#include <cstdint>

#define NSTEPS 2176
#define BURN   128
#define DWALK  512
#define HMLP   1024

// ---------------- scratch (no allocations allowed) ----------------
__device__ __align__(16) float g_M [NSTEPS * DWALK];   // 0.1 * noise_t  [2176,512]
__device__ __align__(16) float g_ZD[NSTEPS * HMLP];    // M @ W1         [2176,1024]
__device__ float g_U[NSTEPS];                          // uniform u_t

// ---------------- threefry2x32 (Random123 / JAX exact) ----------------
__device__ __forceinline__ uint32_t rotl32(uint32_t x, int r) {
    return (x << r) | (x >> (32 - r));
}

__device__ __forceinline__ void threefry2x32(uint32_t k0, uint32_t k1,
                                             uint32_t c0, uint32_t c1,
                                             uint32_t& o0, uint32_t& o1) {
    uint32_t ks2 = 0x1BD11BDAu ^ k0 ^ k1;
    uint32_t x0 = c0 + k0;
    uint32_t x1 = c1 + k1;
#define TF_RND(r) { x0 += x1; x1 = rotl32(x1, r); x1 ^= x0; }
    TF_RND(13) TF_RND(15) TF_RND(26) TF_RND(6)
    x0 += k1;  x1 += ks2 + 1u;
    TF_RND(17) TF_RND(29) TF_RND(16) TF_RND(24)
    x0 += ks2; x1 += k0 + 2u;
    TF_RND(13) TF_RND(15) TF_RND(26) TF_RND(6)
    x0 += k0;  x1 += k1 + 3u;
    TF_RND(17) TF_RND(29) TF_RND(16) TF_RND(24)
    x0 += k1;  x1 += ks2 + 4u;
    TF_RND(13) TF_RND(15) TF_RND(26) TF_RND(6)
    x0 += ks2; x1 += k0 + 5u;
#undef TF_RND
    o0 = x0; o1 = x1;
}

// bits -> float in [0,1): ((b>>9)|0x3f800000) as float - 1  (JAX _uniform)
__device__ __forceinline__ float bits_to_f01(uint32_t b) {
    return __fadd_rn(__uint_as_float((b >> 9) | 0x3F800000u), -1.0f);
}

// XLA ErfInv f32 (Giles polynomial; XLA emits mul+add WITHOUT fma contraction)
__device__ __forceinline__ float erfinv_xla(float x) {
    float w = -log1pf(-__fmul_rn(x, x));
    float p;
    if (w < 5.0f) {
        w = __fadd_rn(w, -2.5f);
        p = 2.81022636e-08f;
        p = __fadd_rn(__fmul_rn(p, w), 3.43273939e-07f);
        p = __fadd_rn(__fmul_rn(p, w), -3.5233877e-06f);
        p = __fadd_rn(__fmul_rn(p, w), -4.39150654e-06f);
        p = __fadd_rn(__fmul_rn(p, w), 0.00021858087f);
        p = __fadd_rn(__fmul_rn(p, w), -0.00125372503f);
        p = __fadd_rn(__fmul_rn(p, w), -0.00417768164f);
        p = __fadd_rn(__fmul_rn(p, w), 0.246640727f);
        p = __fadd_rn(__fmul_rn(p, w), 1.50140941f);
    } else {
        w = __fadd_rn(__fsqrt_rn(w), -3.0f);
        p = -0.000200214257f;
        p = __fadd_rn(__fmul_rn(p, w), 0.000100950558f);
        p = __fadd_rn(__fmul_rn(p, w), 0.00134934322f);
        p = __fadd_rn(__fmul_rn(p, w), -0.00367342844f);
        p = __fadd_rn(__fmul_rn(p, w), 0.00573950773f);
        p = __fadd_rn(__fmul_rn(p, w), -0.0076224613f);
        p = __fadd_rn(__fmul_rn(p, w), 0.00943887047f);
        p = __fadd_rn(__fmul_rn(p, w), 1.00167406f);
        p = __fadd_rn(__fmul_rn(p, w), 2.83297682f);
    }
    return __fmul_rn(p, x);
}

// JAX normal: u = uniform(key, lo=nextafter(-1,0), hi=1); sqrt(2)*erfinv(u)
__device__ __forceinline__ float normal_from_bits(uint32_t b) {
    const float lo = -0.99999994f;  // nextafter(-1f, 0f)
    float f = bits_to_f01(b);
    float u = fmaxf(lo, __fadd_rn(__fmul_rn(f, 2.0f), lo));
    return __fmul_rn(1.4142135381698608f, erfinv_xla(u));  // float32(sqrt(2))
}

#define TANH_CLAMP 7.90531110763549805f

// XLA Tanh f32 emitter (scalar; used in one-time init paths)
__device__ __forceinline__ float tanh_xla(float x) {
    float xc = fminf(fmaxf(x, -TANH_CLAMP), TANH_CLAMP);
    float x2 = __fmul_rn(xc, xc);
    float p = -2.76076847742355e-16f;
    p = __fadd_rn(__fmul_rn(p, x2), 2.00018790482477e-13f);
    p = __fadd_rn(__fmul_rn(p, x2), -8.60467152213735e-11f);
    p = __fadd_rn(__fmul_rn(p, x2), 5.12229709037114e-08f);
    p = __fadd_rn(__fmul_rn(p, x2), 1.48572235717979e-05f);
    p = __fadd_rn(__fmul_rn(p, x2), 6.37261928875436e-04f);
    p = __fadd_rn(__fmul_rn(p, x2), 4.89352455891786e-03f);
    float num = __fmul_rn(xc, p);
    float q = 1.19825839466702e-06f;
    q = __fadd_rn(__fmul_rn(q, x2), 1.18534705686654e-04f);
    q = __fadd_rn(__fmul_rn(q, x2), 2.26843463243900e-03f);
    q = __fadd_rn(__fmul_rn(q, x2), 4.89352518554385e-03f);
    float r = __fdiv_rn(num, q);
    return (fabsf(x) < 0.0004f) ? x : r;
}

// ---------------- packed f32x2 helpers (per-lane IEEE rn => bit-exact) ----------
typedef unsigned long long u64;
__device__ __forceinline__ u64 pk2(float lo, float hi) {
    u64 r; asm("mov.b64 %0, {%1, %2};" : "=l"(r) : "f"(lo), "f"(hi)); return r;
}
__device__ __forceinline__ void upk2(u64 v, float& lo, float& hi) {
    asm("mov.b64 {%0, %1}, %2;" : "=f"(lo), "=f"(hi) : "l"(v));
}
__device__ __forceinline__ u64 mul2(u64 a, u64 b) {
    u64 r; asm("mul.rn.f32x2 %0, %1, %2;" : "=l"(r) : "l"(a), "l"(b)); return r;
}
__device__ __forceinline__ u64 add2(u64 a, u64 b) {
    u64 r; asm("add.rn.f32x2 %0, %1, %2;" : "=l"(r) : "l"(a), "l"(b)); return r;
}

struct TanhC {  // broadcast-packed coefficients, live in registers across the loop
    u64 p0, p1, p2, p3, p4, p5, p6;
    u64 q0, q1, q2, q3;
};
__device__ __forceinline__ TanhC make_tanhc() {
    TanhC c;
    c.p0 = pk2(-2.76076847742355e-16f, -2.76076847742355e-16f);
    c.p1 = pk2( 2.00018790482477e-13f,  2.00018790482477e-13f);
    c.p2 = pk2(-8.60467152213735e-11f, -8.60467152213735e-11f);
    c.p3 = pk2( 5.12229709037114e-08f,  5.12229709037114e-08f);
    c.p4 = pk2( 1.48572235717979e-05f,  1.48572235717979e-05f);
    c.p5 = pk2( 6.37261928875436e-04f,  6.37261928875436e-04f);
    c.p6 = pk2( 4.89352455891786e-03f,  4.89352455891786e-03f);
    c.q0 = pk2( 1.19825839466702e-06f,  1.19825839466702e-06f);
    c.q1 = pk2( 1.18534705686654e-04f,  1.18534705686654e-04f);
    c.q2 = pk2( 2.26843463243900e-03f,  2.26843463243900e-03f);
    c.q3 = pk2( 4.89352518554385e-03f,  4.89352518554385e-03f);
    return c;
}

// tanh_xla on two values; polynomial evaluated packed, bit-identical per lane.
__device__ __forceinline__ void tanh2_xla(float a, float b, const TanhC& C,
                                          float& ra, float& rb) {
    float xc0 = fminf(fmaxf(a, -TANH_CLAMP), TANH_CLAMP);
    float xc1 = fminf(fmaxf(b, -TANH_CLAMP), TANH_CLAMP);
    u64 X  = pk2(xc0, xc1);
    u64 X2 = mul2(X, X);
    u64 P  = C.p0;
    P = add2(mul2(P, X2), C.p1);
    P = add2(mul2(P, X2), C.p2);
    P = add2(mul2(P, X2), C.p3);
    P = add2(mul2(P, X2), C.p4);
    P = add2(mul2(P, X2), C.p5);
    P = add2(mul2(P, X2), C.p6);
    u64 NUM = mul2(X, P);
    u64 Q = C.q0;
    Q = add2(mul2(Q, X2), C.q1);
    Q = add2(mul2(Q, X2), C.q2);
    Q = add2(mul2(Q, X2), C.q3);
    float n0, n1, q0, q1;
    upk2(NUM, n0, n1);
    upk2(Q,   q0, q1);
    float r0 = __fdiv_rn(n0, q0);
    float r1 = __fdiv_rn(n1, q1);
    ra = (fabsf(a) < 0.0004f) ? a : r0;
    rb = (fabsf(b) < 0.0004f) ? b : r1;
}

// ---------------- kernel 1: per-step keys, uniforms, normals ----------------
// jax_threefry_partitionable=True semantics (verified passing R3/R6):
//   split(key, n)[t]             = output pair of TF(key, (0, t))
//   random_bits(key,32,shape)[i] = o0 ^ o1 of TF(key, (0, i))
__global__ void gen_kernel() {
    int t = blockIdx.x;
    int i = threadIdx.x;  // 0..511

    uint32_t kt0, kt1, kn0, kn1;
    threefry2x32(0u, 1u, 0u, (uint32_t)t, kt0, kt1);
    threefry2x32(kt0, kt1, 0u, 0u, kn0, kn1);

    if (i == 0) {
        uint32_t ku0, ku1, ua, ub;
        threefry2x32(kt0, kt1, 0u, 1u, ku0, ku1);
        threefry2x32(ku0, ku1, 0u, 0u, ua, ub);
        g_U[t] = bits_to_f01(ua ^ ub);
    }

    uint32_t r0, r1;
    threefry2x32(kn0, kn1, 0u, (uint32_t)i, r0, r1);
    g_M[t * DWALK + i] = __fmul_rn(normal_from_bits(r0 ^ r1), 0.1f);
}

// ---------------- kernel 2: fp32 SGEMM  ZD = M @ W1 ----------------
// 128x128x8 tile, 256 threads, 8x8 per-thread microtile. 136 blocks ~ 1 wave.
__global__ void __launch_bounds__(256) gemm_kernel(const float* __restrict__ W1) {
    __shared__ float As[8][128];
    __shared__ float Bs[8][128];

    int tid = threadIdx.x;
    int tx = tid & 15;
    int ty = tid >> 4;
    int rowBase = blockIdx.y * 128;
    int colBase = blockIdx.x * 128;

    int aRow = tid >> 1;
    int aK   = (tid & 1) * 4;
    int bK   = tid >> 5;
    int bCol = (tid & 31) * 4;

    float acc[8][8] = {{0.f}};

    for (int k0 = 0; k0 < 512; k0 += 8) {
        float4 av = *reinterpret_cast<const float4*>(&g_M[(rowBase + aRow) * 512 + k0 + aK]);
        float4 bv = *reinterpret_cast<const float4*>(&W1[(k0 + bK) * 1024 + colBase + bCol]);
        As[aK + 0][aRow] = av.x;
        As[aK + 1][aRow] = av.y;
        As[aK + 2][aRow] = av.z;
        As[aK + 3][aRow] = av.w;
        *reinterpret_cast<float4*>(&Bs[bK][bCol]) = bv;
        __syncthreads();
#pragma unroll
        for (int k = 0; k < 8; k++) {
            float4 a0 = *reinterpret_cast<float4*>(&As[k][ty * 8]);
            float4 a1 = *reinterpret_cast<float4*>(&As[k][ty * 8 + 4]);
            float4 b0 = *reinterpret_cast<float4*>(&Bs[k][tx * 8]);
            float4 b1 = *reinterpret_cast<float4*>(&Bs[k][tx * 8 + 4]);
            float ar[8] = {a0.x, a0.y, a0.z, a0.w, a1.x, a1.y, a1.z, a1.w};
            float br[8] = {b0.x, b0.y, b0.z, b0.w, b1.x, b1.y, b1.z, b1.w};
#pragma unroll
            for (int i = 0; i < 8; i++)
#pragma unroll
                for (int j = 0; j < 8; j++)
                    acc[i][j] = fmaf(ar[i], br[j], acc[i][j]);
        }
        __syncthreads();
    }
#pragma unroll
    for (int i = 0; i < 8; i++) {
        int r = rowBase + ty * 8 + i;
        *reinterpret_cast<float4*>(&g_ZD[r * 1024 + colBase + tx * 8]) =
            make_float4(acc[i][0], acc[i][1], acc[i][2], acc[i][3]);
        *reinterpret_cast<float4*>(&g_ZD[r * 1024 + colBase + tx * 8 + 4]) =
            make_float4(acc[i][4], acc[i][5], acc[i][6], acc[i][7]);
    }
}

// ---------------- kernel 3: sequential MH chain (1 CTA, 256 threads) ------------
// Issue-throughput optimized: 8 warps (2/SMSP), 4 hidden units + 2 walker dims
// per thread, packed-f32x2 tanh polynomials, one barrier per step, tree8 combine.
__global__ void __launch_bounds__(256, 1)
chain_kernel(const float* __restrict__ x0, const float* __restrict__ W1,
             const float* __restrict__ b1, const float* __restrict__ W2,
             const float* __restrict__ b2, float* __restrict__ out) {
    __shared__ float s_x0[DWALK];
    __shared__ __align__(16) float s_part[2][8];

    int tid  = threadIdx.x;          // 0..255
    int lane = tid & 31;
    int wid  = tid >> 5;             // 0..7

    s_x0[tid]       = x0[tid];
    s_x0[tid + 256] = x0[tid + 256];
    __syncthreads();

    const TanhC TC = make_tanhc();

    // z_i = dot(x0, W1[:, 4*tid + i]), i = 0..3
    float z0 = 0.f, z1 = 0.f, z2 = 0.f, z3 = 0.f;
#pragma unroll 4
    for (int k = 0; k < DWALK; k++) {
        float xv = s_x0[k];
        float4 w = *reinterpret_cast<const float4*>(&W1[k * HMLP + 4 * tid]);
        z0 = fmaf(xv, w.x, z0);
        z1 = fmaf(xv, w.y, z1);
        z2 = fmaf(xv, w.z, z2);
        z3 = fmaf(xv, w.w, z3);
    }

    float4 b1v = *reinterpret_cast<const float4*>(&b1[4 * tid]);
    float4 w2v = *reinterpret_cast<const float4*>(&W2[4 * tid]);
    float  b2v = b2[0];
    float2 x   = make_float2(s_x0[2 * tid], s_x0[2 * tid + 1]);

    // fixed-order sum of 8 warp partials (identical on every thread)
    auto tree8 = [&](const float* sp) -> float {
        float4 q0 = *reinterpret_cast<const float4*>(sp);
        float4 q1 = *reinterpret_cast<const float4*>(sp + 4);
        float s0 = __fadd_rn(__fadd_rn(q0.x, q0.y), __fadd_rn(q0.z, q0.w));
        float s1 = __fadd_rn(__fadd_rn(q1.x, q1.y), __fadd_rn(q1.z, q1.w));
        return __fadd_rn(s0, s1);
    };

    // ---- p_old = psi2(x0) ----
    float p_old;
    {
        float h0 = tanh_xla(__fadd_rn(z0, b1v.x));
        float h1 = tanh_xla(__fadd_rn(z1, b1v.y));
        float h2 = tanh_xla(__fadd_rn(z2, b1v.z));
        float h3 = tanh_xla(__fadd_rn(z3, b1v.w));
        float pv = __fadd_rn(__fadd_rn(__fmul_rn(h0, w2v.x), __fmul_rn(h1, w2v.y)),
                             __fadd_rn(__fmul_rn(h2, w2v.z), __fmul_rn(h3, w2v.w)));
#pragma unroll
        for (int o = 16; o > 0; o >>= 1) pv += __shfl_down_sync(0xffffffffu, pv, o);
        if (lane == 0) s_part[1][wid] = pv;
        __syncthreads();
        float mdl = __fadd_rn(tree8(s_part[1]), b2v);
        p_old = __fmul_rn(mdl, mdl);
    }
    __syncthreads();   // all reads of s_part[1] complete before iter 1 rewrites it

    // row pointers (advance by one row per step; t-indexed, accept-independent)
    const float4* pZD = reinterpret_cast<const float4*>(g_ZD) + tid;   // row stride 256
    const float2* pM  = reinterpret_cast<const float2*>(g_M) + tid;    // row stride 256
    float2* pOut = reinterpret_cast<float2*>(out) + tid;               // row stride 256

    // prefetch step 0
    float4 zd = pZD[0];
    float2 mv = pM[0];
    float  uv = g_U[0];

    for (int t = 0; t < NSTEPS; t++) {
        float znew0 = __fadd_rn(z0, zd.x);
        float znew1 = __fadd_rn(z1, zd.y);
        float znew2 = __fadd_rn(z2, zd.z);
        float znew3 = __fadd_rn(z3, zd.w);

        float h0, h1, h2, h3;
        tanh2_xla(__fadd_rn(znew0, b1v.x), __fadd_rn(znew1, b1v.y), TC, h0, h1);
        tanh2_xla(__fadd_rn(znew2, b1v.z), __fadd_rn(znew3, b1v.w), TC, h2, h3);

        float pv = __fadd_rn(__fadd_rn(__fmul_rn(h0, w2v.x), __fmul_rn(h1, w2v.y)),
                             __fadd_rn(__fmul_rn(h2, w2v.z), __fmul_rn(h3, w2v.w)));

        // prefetch next step
        float4 zd_n = make_float4(0.f, 0.f, 0.f, 0.f);
        float2 m_n  = make_float2(0.f, 0.f);
        float  u_n  = 0.f;
        if (t + 1 < NSTEPS) {
            zd_n = pZD[(size_t)(t + 1) * 256];
            m_n  = pM [(size_t)(t + 1) * 256];
            u_n  = g_U[t + 1];
        }

#pragma unroll
        for (int o = 16; o > 0; o >>= 1) pv += __shfl_down_sync(0xffffffffu, pv, o);
        if (lane == 0) s_part[t & 1][wid] = pv;
        __syncthreads();

        float mdl   = __fadd_rn(tree8(s_part[t & 1]), b2v);
        float p_new = __fmul_rn(mdl, mdl);
        float ratio = fminf(__fdiv_rn(p_new, __fadd_rn(p_old, 1e-12f)), 1.0f);
        bool  acc   = (uv < ratio);

        if (acc) {
            p_old = p_new;
            z0 = znew0; z1 = znew1; z2 = znew2; z3 = znew3;
            x.x = __fadd_rn(x.x, mv.x);
            x.y = __fadd_rn(x.y, mv.y);
        }
        if (t >= BURN) pOut[(size_t)(t - BURN) * 256] = x;

        zd = zd_n; mv = m_n; uv = u_n;
    }
}

// ---------------- launch ----------------
extern "C" void kernel_launch(void* const* d_in, const int* in_sizes, int n_in,
                              void* d_out, int out_size) {
    const float* x0 = (const float*)d_in[0];
    const float* W1 = (const float*)d_in[1];
    const float* b1 = (const float*)d_in[2];
    const float* W2 = (const float*)d_in[3];
    const float* b2 = (const float*)d_in[4];
    float* out = (float*)d_out;

    gen_kernel<<<NSTEPS, DWALK>>>();
    gemm_kernel<<<dim3(HMLP / 128, NSTEPS / 128), 256>>>(W1);
    chain_kernel<<<1, 256>>>(x0, W1, b1, W2, b2, out);
}

// round 13
// speedup vs baseline: 1.4519x; 1.0553x over previous
#include <cuda_runtime.h>
#include <cstdint>

#define NSTEPS 2176
#define BURN   128
#define DWALK  512
#define HMLP   1024

// ---------------- scratch (no allocations allowed) ----------------
__device__ __align__(16) float g_M [NSTEPS * DWALK];   // 0.1 * noise_t  [2176,512]
__device__ __align__(16) float g_ZD[NSTEPS * HMLP];    // M @ W1         [2176,1024]
__device__ float g_U[NSTEPS];                          // uniform u_t

// ---------------- threefry2x32 (Random123 / JAX exact) ----------------
__device__ __forceinline__ uint32_t rotl32(uint32_t x, int r) {
    return (x << r) | (x >> (32 - r));
}

__device__ __forceinline__ void threefry2x32(uint32_t k0, uint32_t k1,
                                             uint32_t c0, uint32_t c1,
                                             uint32_t& o0, uint32_t& o1) {
    uint32_t ks2 = 0x1BD11BDAu ^ k0 ^ k1;
    uint32_t x0 = c0 + k0;
    uint32_t x1 = c1 + k1;
#define TF_RND(r) { x0 += x1; x1 = rotl32(x1, r); x1 ^= x0; }
    TF_RND(13) TF_RND(15) TF_RND(26) TF_RND(6)
    x0 += k1;  x1 += ks2 + 1u;
    TF_RND(17) TF_RND(29) TF_RND(16) TF_RND(24)
    x0 += ks2; x1 += k0 + 2u;
    TF_RND(13) TF_RND(15) TF_RND(26) TF_RND(6)
    x0 += k0;  x1 += k1 + 3u;
    TF_RND(17) TF_RND(29) TF_RND(16) TF_RND(24)
    x0 += k1;  x1 += ks2 + 4u;
    TF_RND(13) TF_RND(15) TF_RND(26) TF_RND(6)
    x0 += ks2; x1 += k0 + 5u;
#undef TF_RND
    o0 = x0; o1 = x1;
}

// bits -> float in [0,1): ((b>>9)|0x3f800000) as float - 1  (JAX _uniform)
__device__ __forceinline__ float bits_to_f01(uint32_t b) {
    return __fadd_rn(__uint_as_float((b >> 9) | 0x3F800000u), -1.0f);
}

// XLA ErfInv f32 (Giles polynomial; XLA emits mul+add WITHOUT fma contraction)
__device__ __forceinline__ float erfinv_xla(float x) {
    float w = -log1pf(-__fmul_rn(x, x));
    float p;
    if (w < 5.0f) {
        w = __fadd_rn(w, -2.5f);
        p = 2.81022636e-08f;
        p = __fadd_rn(__fmul_rn(p, w), 3.43273939e-07f);
        p = __fadd_rn(__fmul_rn(p, w), -3.5233877e-06f);
        p = __fadd_rn(__fmul_rn(p, w), -4.39150654e-06f);
        p = __fadd_rn(__fmul_rn(p, w), 0.00021858087f);
        p = __fadd_rn(__fmul_rn(p, w), -0.00125372503f);
        p = __fadd_rn(__fmul_rn(p, w), -0.00417768164f);
        p = __fadd_rn(__fmul_rn(p, w), 0.246640727f);
        p = __fadd_rn(__fmul_rn(p, w), 1.50140941f);
    } else {
        w = __fadd_rn(__fsqrt_rn(w), -3.0f);
        p = -0.000200214257f;
        p = __fadd_rn(__fmul_rn(p, w), 0.000100950558f);
        p = __fadd_rn(__fmul_rn(p, w), 0.00134934322f);
        p = __fadd_rn(__fmul_rn(p, w), -0.00367342844f);
        p = __fadd_rn(__fmul_rn(p, w), 0.00573950773f);
        p = __fadd_rn(__fmul_rn(p, w), -0.0076224613f);
        p = __fadd_rn(__fmul_rn(p, w), 0.00943887047f);
        p = __fadd_rn(__fmul_rn(p, w), 1.00167406f);
        p = __fadd_rn(__fmul_rn(p, w), 2.83297682f);
    }
    return __fmul_rn(p, x);
}

// JAX normal: u = uniform(key, lo=nextafter(-1,0), hi=1); sqrt(2)*erfinv(u)
__device__ __forceinline__ float normal_from_bits(uint32_t b) {
    const float lo = -0.99999994f;  // nextafter(-1f, 0f)
    float f = bits_to_f01(b);
    float u = fmaxf(lo, __fadd_rn(__fmul_rn(f, 2.0f), lo));
    return __fmul_rn(1.4142135381698608f, erfinv_xla(u));  // float32(sqrt(2))
}

#define TANH_CLAMP 7.90531110763549805f

// XLA Tanh f32 emitter (scalar; used in one-time init paths)
__device__ __forceinline__ float tanh_xla(float x) {
    float xc = fminf(fmaxf(x, -TANH_CLAMP), TANH_CLAMP);
    float x2 = __fmul_rn(xc, xc);
    float p = -2.76076847742355e-16f;
    p = __fadd_rn(__fmul_rn(p, x2), 2.00018790482477e-13f);
    p = __fadd_rn(__fmul_rn(p, x2), -8.60467152213735e-11f);
    p = __fadd_rn(__fmul_rn(p, x2), 5.12229709037114e-08f);
    p = __fadd_rn(__fmul_rn(p, x2), 1.48572235717979e-05f);
    p = __fadd_rn(__fmul_rn(p, x2), 6.37261928875436e-04f);
    p = __fadd_rn(__fmul_rn(p, x2), 4.89352455891786e-03f);
    float num = __fmul_rn(xc, p);
    float q = 1.19825839466702e-06f;
    q = __fadd_rn(__fmul_rn(q, x2), 1.18534705686654e-04f);
    q = __fadd_rn(__fmul_rn(q, x2), 2.26843463243900e-03f);
    q = __fadd_rn(__fmul_rn(q, x2), 4.89352518554385e-03f);
    float r = __fdiv_rn(num, q);
    return (fabsf(x) < 0.0004f) ? x : r;
}

// ---------------- packed f32x2 helpers (per-lane IEEE rn => bit-exact) ----------
typedef unsigned long long u64;
__device__ __forceinline__ u64 pk2(float lo, float hi) {
    u64 r; asm("mov.b64 %0, {%1, %2};" : "=l"(r) : "f"(lo), "f"(hi)); return r;
}
__device__ __forceinline__ void upk2(u64 v, float& lo, float& hi) {
    asm("mov.b64 {%0, %1}, %2;" : "=f"(lo), "=f"(hi) : "l"(v));
}
__device__ __forceinline__ u64 mul2(u64 a, u64 b) {
    u64 r; asm("mul.rn.f32x2 %0, %1, %2;" : "=l"(r) : "l"(a), "l"(b)); return r;
}
__device__ __forceinline__ u64 add2(u64 a, u64 b) {
    u64 r; asm("add.rn.f32x2 %0, %1, %2;" : "=l"(r) : "l"(a), "l"(b)); return r;
}

struct TanhC {  // broadcast-packed coefficients, live in registers across the loop
    u64 p0, p1, p2, p3, p4, p5, p6;
    u64 q0, q1, q2, q3;
};
__device__ __forceinline__ TanhC make_tanhc() {
    TanhC c;
    c.p0 = pk2(-2.76076847742355e-16f, -2.76076847742355e-16f);
    c.p1 = pk2( 2.00018790482477e-13f,  2.00018790482477e-13f);
    c.p2 = pk2(-8.60467152213735e-11f, -8.60467152213735e-11f);
    c.p3 = pk2( 5.12229709037114e-08f,  5.12229709037114e-08f);
    c.p4 = pk2( 1.48572235717979e-05f,  1.48572235717979e-05f);
    c.p5 = pk2( 6.37261928875436e-04f,  6.37261928875436e-04f);
    c.p6 = pk2( 4.89352455891786e-03f,  4.89352455891786e-03f);
    c.q0 = pk2( 1.19825839466702e-06f,  1.19825839466702e-06f);
    c.q1 = pk2( 1.18534705686654e-04f,  1.18534705686654e-04f);
    c.q2 = pk2( 2.26843463243900e-03f,  2.26843463243900e-03f);
    c.q3 = pk2( 4.89352518554385e-03f,  4.89352518554385e-03f);
    return c;
}

// tanh_xla on two values; polynomial evaluated packed, bit-identical per lane.
// (Empirically validated bit-exact vs scalar tanh_xla in R9: identical rel_err.)
__device__ __forceinline__ void tanh2_xla(float a, float b, const TanhC& C,
                                          float& ra, float& rb) {
    float xc0 = fminf(fmaxf(a, -TANH_CLAMP), TANH_CLAMP);
    float xc1 = fminf(fmaxf(b, -TANH_CLAMP), TANH_CLAMP);
    u64 X  = pk2(xc0, xc1);
    u64 X2 = mul2(X, X);
    u64 P  = C.p0;
    P = add2(mul2(P, X2), C.p1);
    P = add2(mul2(P, X2), C.p2);
    P = add2(mul2(P, X2), C.p3);
    P = add2(mul2(P, X2), C.p4);
    P = add2(mul2(P, X2), C.p5);
    P = add2(mul2(P, X2), C.p6);
    u64 NUM = mul2(X, P);
    u64 Q = C.q0;
    Q = add2(mul2(Q, X2), C.q1);
    Q = add2(mul2(Q, X2), C.q2);
    Q = add2(mul2(Q, X2), C.q3);
    float n0, n1, q0, q1;
    upk2(NUM, n0, n1);
    upk2(Q,   q0, q1);
    float r0 = __fdiv_rn(n0, q0);
    float r1 = __fdiv_rn(n1, q1);
    ra = (fabsf(a) < 0.0004f) ? a : r0;
    rb = (fabsf(b) < 0.0004f) ? b : r1;
}

// ---------------- kernel 1: per-step keys, uniforms, normals ----------------
// jax_threefry_partitionable=True semantics (verified passing R3/R6/R9):
//   split(key, n)[t]             = output pair of TF(key, (0, t))
//   random_bits(key,32,shape)[i] = o0 ^ o1 of TF(key, (0, i))
__global__ void gen_kernel() {
    int t = blockIdx.x;
    int i = threadIdx.x;  // 0..511

    uint32_t kt0, kt1, kn0, kn1;
    threefry2x32(0u, 1u, 0u, (uint32_t)t, kt0, kt1);
    threefry2x32(kt0, kt1, 0u, 0u, kn0, kn1);

    if (i == 0) {
        uint32_t ku0, ku1, ua, ub;
        threefry2x32(kt0, kt1, 0u, 1u, ku0, ku1);
        threefry2x32(ku0, ku1, 0u, 0u, ua, ub);
        g_U[t] = bits_to_f01(ua ^ ub);
    }

    uint32_t r0, r1;
    threefry2x32(kn0, kn1, 0u, (uint32_t)i, r0, r1);
    g_M[t * DWALK + i] = __fmul_rn(normal_from_bits(r0 ^ r1), 0.1f);
}

// ---------------- kernel 2: fp32 SGEMM  ZD = M @ W1 ----------------
// 128x128x8 tile, 256 threads, 8x8 per-thread microtile. 136 blocks ~ 1 wave.
__global__ void __launch_bounds__(256) gemm_kernel(const float* __restrict__ W1) {
    __shared__ float As[8][128];
    __shared__ float Bs[8][128];

    int tid = threadIdx.x;
    int tx = tid & 15;
    int ty = tid >> 4;
    int rowBase = blockIdx.y * 128;
    int colBase = blockIdx.x * 128;

    int aRow = tid >> 1;
    int aK   = (tid & 1) * 4;
    int bK   = tid >> 5;
    int bCol = (tid & 31) * 4;

    float acc[8][8] = {{0.f}};

    for (int k0 = 0; k0 < 512; k0 += 8) {
        float4 av = *reinterpret_cast<const float4*>(&g_M[(rowBase + aRow) * 512 + k0 + aK]);
        float4 bv = *reinterpret_cast<const float4*>(&W1[(k0 + bK) * 1024 + colBase + bCol]);
        As[aK + 0][aRow] = av.x;
        As[aK + 1][aRow] = av.y;
        As[aK + 2][aRow] = av.z;
        As[aK + 3][aRow] = av.w;
        *reinterpret_cast<float4*>(&Bs[bK][bCol]) = bv;
        __syncthreads();
#pragma unroll
        for (int k = 0; k < 8; k++) {
            float4 a0 = *reinterpret_cast<float4*>(&As[k][ty * 8]);
            float4 a1 = *reinterpret_cast<float4*>(&As[k][ty * 8 + 4]);
            float4 b0 = *reinterpret_cast<float4*>(&Bs[k][tx * 8]);
            float4 b1 = *reinterpret_cast<float4*>(&Bs[k][tx * 8 + 4]);
            float ar[8] = {a0.x, a0.y, a0.z, a0.w, a1.x, a1.y, a1.z, a1.w};
            float br[8] = {b0.x, b0.y, b0.z, b0.w, b1.x, b1.y, b1.z, b1.w};
#pragma unroll
            for (int i = 0; i < 8; i++)
#pragma unroll
                for (int j = 0; j < 8; j++)
                    acc[i][j] = fmaf(ar[i], br[j], acc[i][j]);
        }
        __syncthreads();
    }
#pragma unroll
    for (int i = 0; i < 8; i++) {
        int r = rowBase + ty * 8 + i;
        *reinterpret_cast<float4*>(&g_ZD[r * 1024 + colBase + tx * 8]) =
            make_float4(acc[i][0], acc[i][1], acc[i][2], acc[i][3]);
        *reinterpret_cast<float4*>(&g_ZD[r * 1024 + colBase + tx * 8 + 4]) =
            make_float4(acc[i][4], acc[i][5], acc[i][6], acc[i][7]);
    }
}

// ---------------- kernel 3: sequential MH chain (1 CTA, 512 threads) ------------
// R6 shape (16 warps, 2 units/thread, tree16, one barrier/step) with packed-f32x2
// z-state and tanh math => fewer instructions at same latency-hiding. Decision
// sequence is bit-identical to R6 (same pv order, same tree16, fmin dropped
// because u in [0,1) makes it decision-equivalent).
__global__ void __launch_bounds__(512, 1)
chain_kernel(const float* __restrict__ x0, const float* __restrict__ W1,
             const float* __restrict__ b1, const float* __restrict__ W2,
             const float* __restrict__ b2, float* __restrict__ out) {
    __shared__ float s_x0[DWALK];
    __shared__ __align__(16) float s_part[2][16];

    int tid  = threadIdx.x;          // 0..511
    int lane = tid & 31;
    int wid  = tid >> 5;             // 0..15

    s_x0[tid] = x0[tid];
    __syncthreads();

    const TanhC TC = make_tanhc();

    // z = dot(x0, W1[:, 2*tid]), dot(x0, W1[:, 2*tid+1])
    float zc0 = 0.f, zc1 = 0.f;
#pragma unroll 8
    for (int k = 0; k < DWALK; k++) {
        float xv = s_x0[k];
        float2 w = *reinterpret_cast<const float2*>(&W1[k * 1024 + 2 * tid]);
        zc0 = fmaf(xv, w.x, zc0);
        zc1 = fmaf(xv, w.y, zc1);
    }

    float2 b1v = *reinterpret_cast<const float2*>(&b1[2 * tid]);
    float2 w2v = *reinterpret_cast<const float2*>(&W2[2 * tid]);
    float  b2v = b2[0];
    float  x   = s_x0[tid];

    auto tree16 = [&](const float* sp) -> float {
        float4 q0 = *reinterpret_cast<const float4*>(sp);
        float4 q1 = *reinterpret_cast<const float4*>(sp + 4);
        float4 q2 = *reinterpret_cast<const float4*>(sp + 8);
        float4 q3 = *reinterpret_cast<const float4*>(sp + 12);
        float s0 = __fadd_rn(__fadd_rn(q0.x, q0.y), __fadd_rn(q0.z, q0.w));
        float s1 = __fadd_rn(__fadd_rn(q1.x, q1.y), __fadd_rn(q1.z, q1.w));
        float s2 = __fadd_rn(__fadd_rn(q2.x, q2.y), __fadd_rn(q2.z, q2.w));
        float s3 = __fadd_rn(__fadd_rn(q3.x, q3.y), __fadd_rn(q3.z, q3.w));
        return __fadd_rn(__fadd_rn(s0, s1), __fadd_rn(s2, s3));
    };

    // ---- p_old = psi2(x0) ----
    float p_old;
    {
        float h0 = tanh_xla(__fadd_rn(zc0, b1v.x));
        float h1 = tanh_xla(__fadd_rn(zc1, b1v.y));
        float pv = __fadd_rn(__fmul_rn(h0, w2v.x), __fmul_rn(h1, w2v.y));
#pragma unroll
        for (int o = 16; o > 0; o >>= 1) pv += __shfl_down_sync(0xffffffffu, pv, o);
        if (lane == 0) s_part[1][wid] = pv;
        __syncthreads();
        float mdl = __fadd_rn(tree16(s_part[1]), b2v);
        p_old = __fmul_rn(mdl, mdl);
    }
    __syncthreads();   // all reads of s_part[1] done before iter 1 rewrites it

    // packed carried state
    u64 Z   = pk2(zc0, zc1);
    u64 B1P = pk2(b1v.x, b1v.y);

    // row pointers (t-indexed only, accept-independent)
    const u64* pZD = reinterpret_cast<const u64*>(g_ZD) + tid;   // row stride 512 u64
    const float* pM = g_M + tid;                                 // row stride 512

    // prefetch step 0
    u64   ZD = pZD[0];
    float mv = pM[0];
    float uv = g_U[0];

    for (int t = 0; t < NSTEPS; t++) {
        u64 ZNEW = add2(Z, ZD);
        u64 A    = add2(ZNEW, B1P);
        float a0, a1, h0, h1;
        upk2(A, a0, a1);
        tanh2_xla(a0, a1, TC, h0, h1);
        float pv = __fadd_rn(__fmul_rn(h0, w2v.x), __fmul_rn(h1, w2v.y));

        // prefetch next step
        u64   zd_n = 0ull;
        float m_n = 0.f, u_n = 0.f;
        if (t + 1 < NSTEPS) {
            zd_n = pZD[(size_t)(t + 1) * 512];
            m_n  = pM [(size_t)(t + 1) * 512];
            u_n  = g_U[t + 1];
        }

#pragma unroll
        for (int o = 16; o > 0; o >>= 1) pv += __shfl_down_sync(0xffffffffu, pv, o);
        if (lane == 0) s_part[t & 1][wid] = pv;
        __syncthreads();

        float mdl   = __fadd_rn(tree16(s_part[t & 1]), b2v);
        float p_new = __fmul_rn(mdl, mdl);
        // u in [0,1): u < min(ratio,1) <=> u < ratio  (fmin dropped, decision-equal)
        float ratio = __fdiv_rn(p_new, __fadd_rn(p_old, 1e-12f));
        bool  acc   = (uv < ratio);

        if (acc) {
            p_old = p_new;
            Z = ZNEW;
            x = __fadd_rn(x, mv);
        }
        if (t >= BURN) out[(size_t)(t - BURN) * DWALK + tid] = x;

        ZD = zd_n; mv = m_n; uv = u_n;
    }
}

// ---------------- launch ----------------
extern "C" void kernel_launch(void* const* d_in, const int* in_sizes, int n_in,
                              void* d_out, int out_size) {
    const float* x0 = (const float*)d_in[0];
    const float* W1 = (const float*)d_in[1];
    const float* b1 = (const float*)d_in[2];
    const float* W2 = (const float*)d_in[3];
    const float* b2 = (const float*)d_in[4];
    float* out = (float*)d_out;

    gen_kernel<<<NSTEPS, DWALK>>>();
    gemm_kernel<<<dim3(HMLP / 128, NSTEPS / 128), 256>>>(W1);
    chain_kernel<<<1, 512>>>(x0, W1, b1, W2, b2, out);
}